// round 15
// baseline (speedup 1.0000x reference)
#include <cuda_runtime.h>

#define HB 40
#define WB 40
#define HWB 1600          // 40*40
#define CIN 256
#define CMID 64
#define CENC 100
#define NBATCH 2

#define XP 44             // padded x row (pad 2 each side)
#define XPP (XP * XP)     // 1936
#define CP 42             // padded comp row (pad 1 each side)
#define CPP (CP * CP)     // 1764

typedef unsigned long long u64;

// Scratch (device globals; zero-initialized, borders never written -> stay 0)
__device__ u64   g_xdup[NBATCH * CIN * XPP];    // (x,x) pairs, padded 44x44
__device__ u64   g_comp_dup[NBATCH * CMID * CPP]; // (v,v) pairs, padded 42x42
__device__ float g_enc[NBATCH * CENC * HWB];    // (b,100,40,40)

// ---- packed fp32x2 helpers (sm_103a FFMA2 via PTX) ----
__device__ __forceinline__ u64 pack2(float x, float y) {
    u64 r; asm("mov.b64 %0, {%1, %2};" : "=l"(r) : "f"(x), "f"(y)); return r;
}
__device__ __forceinline__ void ffma2(u64 &d, u64 a, u64 b) {
    asm("fma.rn.f32x2 %0, %1, %2, %0;" : "+l"(d) : "l"(a), "l"(b));
}
__device__ __forceinline__ float2 unpack2(u64 v) {
    float2 f; asm("mov.b64 {%0, %1}, %2;" : "=f"(f.x), "=f"(f.y) : "l"(v)); return f;
}

// ---------------------------------------------------------------------------
// K1: 1x1 conv, ci-split x8 (smem reduce). Block 640 = 80 px * 8 splits.
// Also: blockIdx.y==0 blocks store the (x,x) dup pairs they already computed
// into g_xdup (padded) for K3. Output comp written as dup pairs (padded) for K2.
// ---------------------------------------------------------------------------
__global__ __launch_bounds__(640) void k1_compress(
    const float* __restrict__ x, const float* __restrict__ wcomp)
{
    __shared__ __align__(16) float ws[CIN * 8];   // [ci][co(8)]
    __shared__ __align__(16) u64 red[7 * 80 * 4]; // splits 1..7 partials

    const int tid   = threadIdx.x;
    const int px    = tid % 80;
    const int split = tid / 80;                   // 0..7
    const int p     = blockIdx.x * 80 + px;       // 20*80 = 1600 = HWB
    const int co0   = blockIdx.y * 8;
    const int b     = blockIdx.z;
    const int ph = p / WB, pw = p % WB;

    for (int i = tid; i < CIN * 8; i += 640) {
        int co = i >> 8, ci = i & 255;            // coalesced read in ci
        ws[ci * 8 + co] = wcomp[(co0 + co) * CIN + ci];
    }
    __syncthreads();

    const int ci0 = split * 32;
    const float* xb = x + (size_t)(b * CIN + ci0) * HWB + p;
    u64* xd = g_xdup + (size_t)(b * CIN + ci0) * XPP + (ph + 2) * XP + (pw + 2);
    const bool dump_x = (blockIdx.y == 0);

    u64 acc0 = 0, acc1 = 0, acc2 = 0, acc3 = 0;   // (0.f,0.f)

    #pragma unroll 16
    for (int ci = 0; ci < 32; ++ci) {
        float xv = xb[(size_t)ci * HWB];
        u64 xx = pack2(xv, xv);
        if (dump_x) xd[(size_t)ci * XPP] = xx;
        const u64* wr = (const u64*)&ws[(ci0 + ci) * 8];  // broadcast LDS.64
        ffma2(acc0, xx, wr[0]);
        ffma2(acc1, xx, wr[1]);
        ffma2(acc2, xx, wr[2]);
        ffma2(acc3, xx, wr[3]);
    }

    if (split > 0) {
        u64* r = &red[((split - 1) * 80 + px) * 4];
        r[0] = acc0; r[1] = acc1; r[2] = acc2; r[3] = acc3;
    }
    __syncthreads();

    if (split == 0) {
        const u64 one = pack2(1.f, 1.f);
        #pragma unroll
        for (int s = 0; s < 7; ++s) {
            const u64* r = &red[(s * 80 + px) * 4];
            ffma2(acc0, one, r[0]);
            ffma2(acc1, one, r[1]);
            ffma2(acc2, one, r[2]);
            ffma2(acc3, one, r[3]);
        }
        u64* cb = g_comp_dup + (size_t)(b * CMID + co0) * CPP + (ph + 1) * CP + (pw + 1);
        float2 v;
        v = unpack2(acc0); cb[0 * CPP] = pack2(v.x, v.x); cb[1 * CPP] = pack2(v.y, v.y);
        v = unpack2(acc1); cb[2 * CPP] = pack2(v.x, v.x); cb[3 * CPP] = pack2(v.y, v.y);
        v = unpack2(acc2); cb[4 * CPP] = pack2(v.x, v.x); cb[5 * CPP] = pack2(v.y, v.y);
        v = unpack2(acc3); cb[6 * CPP] = pack2(v.x, v.x); cb[7 * CPP] = pack2(v.y, v.y);
    }
}

// ---------------------------------------------------------------------------
// K2: 3x3 conv 64->100, pad 1. Block: 8x8 px tile x 10 co, 256 threads.
// x read DIRECTLY from g_comp_dup (padded dup pairs -> no staging, no bounds,
// no pack). Thread = 4 px x 10 co x 4 ci (split 16). Per tap: 4 LDG.64 +
// 5 w-LDS.64 + 20 FFMA2 for 40 MACs. Flat reduce: scatter 5120 partials,
// then 256 threads chain-reduce 16 each and store to g_enc.
// ---------------------------------------------------------------------------
__global__ __launch_bounds__(256) void k2_encoder(const float* __restrict__ wenc)
{
    __shared__ __align__(16) u64 red[320 * 17];   // 43.5KB; ws aliases front
    float* ws = (float*)red;                      // [ci*9+tap][co10], 23KB

    const int tile = blockIdx.x;                  // 0..24
    const int co0  = blockIdx.y * 10;
    const int b    = blockIdx.z;
    const int h0 = (tile / 5) * 8, w0 = (tile % 5) * 8;
    const int tid = threadIdx.x;

    for (int i = tid; i < 5760; i += 256) {
        int c = i / 576, il = i - c * 576;        // coalesced in il
        ws[il * 10 + c] = wenc[(co0 + c) * 576 + il];
    }
    __syncthreads();

    const int pxg   = tid & 15;                   // 16 groups of 4 px
    const int split = tid >> 4;                   // 0..15
    const int row   = pxg >> 1;                   // 0..7
    const int col0  = (pxg & 1) * 4;              // 0 or 4

    u64 acc[5][4];
    #pragma unroll
    for (int j = 0; j < 5; ++j)
        #pragma unroll
        for (int q = 0; q < 4; ++q) acc[j][q] = 0;

    const u64* cpb = g_comp_dup + (size_t)(b * CMID) * CPP
                   + (h0 + row) * CP + (w0 + col0);

    #pragma unroll
    for (int q4 = 0; q4 < 4; ++q4) {
        const int ci = split * 4 + q4;            // 0..63
        const u64*  xrow = cpb + (size_t)ci * CPP;
        const float* wb  = &ws[ci * 90];
        #pragma unroll
        for (int tr = 0; tr < 3; ++tr)
        #pragma unroll
        for (int tc = 0; tc < 3; ++tc) {
            const u64* xr = xrow + tr * CP + tc;
            u64 xx0 = xr[0], xx1 = xr[1], xx2 = xr[2], xx3 = xr[3];
            const u64* wp = (const u64*)(wb + (tr * 3 + tc) * 10);
            #pragma unroll
            for (int j = 0; j < 5; ++j) {
                u64 w = wp[j];
                ffma2(acc[j][0], xx0, w);
                ffma2(acc[j][1], xx1, w);
                ffma2(acc[j][2], xx2, w);
                ffma2(acc[j][3], xx3, w);
            }
        }
    }

    __syncthreads();                              // ws LDS reads complete
    #pragma unroll
    for (int j = 0; j < 5; ++j)
        #pragma unroll
        for (int q = 0; q < 4; ++q)
            red[((pxg * 5 + j) * 4 + q) * 17 + split] = acc[j][q];
    __syncthreads();

    // flat reduce: 320 outputs over 256 threads
    const u64 one = pack2(1.f, 1.f);
    for (int o = tid; o < 320; o += 256) {
        const u64* r = &red[o * 17];
        u64 s = r[0];
        #pragma unroll
        for (int t = 1; t < 16; ++t) ffma2(s, one, r[t]);
        int pxg2 = o / 20, rr = o - pxg2 * 20;
        int j = rr >> 2, q = rr & 3;
        int row2 = pxg2 >> 1, col2 = ((pxg2 & 1) << 2) + q;
        int sp = (h0 + row2) * WB + (w0 + col2);
        float2 v = unpack2(s);
        float* ob = g_enc + (size_t)(b * CENC + co0 + 2 * j) * HWB + sp;
        ob[0]   = v.x;
        ob[HWB] = v.y;
    }
}

// ---------------------------------------------------------------------------
// K3: fused softmax + reassembly. Weight quirk (verified): t2=2*pw+d/2;
// si=t2/40; wc=t2%40; sj=d&1; logit_k = enc[b,k*4+si*2+sj,ph,wc].
// x read from g_xdup (padded dup pairs): per tap = 1 LDG.64 + 2 FFMA2.
// No bounds mask, no packing. grid (50, 4, 2) x 256 threads.
// ---------------------------------------------------------------------------
__global__ __launch_bounds__(256) void k3_reassemble(float* __restrict__ out)
{
    __shared__ __align__(16) float wsm[32 * 104];     // [pl][k*4+d], stride 104

    const int p0 = blockIdx.x * 32;
    const int c0 = blockIdx.y * 64;
    const int b  = blockIdx.z;
    const int tid = threadIdx.x;

    if (tid < 128) {
        const int pl = tid & 31, d = tid >> 5;
        const int p  = p0 + pl;
        const int ph = p / WB, pw = p % WB;
        const int t2 = 2 * pw + (d >> 1);
        const int si = (t2 >= WB) ? 1 : 0;
        const int wc = t2 - WB * si;
        const int sj = d & 1;
        const float* ebase = g_enc + (size_t)(b * CENC + si * 2 + sj) * HWB + ph * WB + wc;

        float v[25];
        #pragma unroll
        for (int k = 0; k < 25; ++k) v[k] = ebase[(size_t)k * 4 * HWB];
        float m = v[0];
        #pragma unroll
        for (int k = 1; k < 25; ++k) m = fmaxf(m, v[k]);
        float s = 0.f;
        #pragma unroll
        for (int k = 0; k < 25; ++k) { v[k] = __expf(v[k] - m); s += v[k]; }
        float inv = 1.f / s;
        #pragma unroll
        for (int k = 0; k < 25; ++k) wsm[pl * 104 + k * 4 + d] = v[k] * inv;
    }
    __syncthreads();

    const int pl = tid & 31, cq = tid >> 5;           // cq 0..7
    const int p  = p0 + pl;
    const int ph = p / WB, pw = p % WB;

    u64 wrA[25], wrB[25];                             // (d0,d1) / (d2,d3)
    #pragma unroll
    for (int k = 0; k < 25; ++k) {
        wrA[k] = *(const u64*)&wsm[pl * 104 + k * 4];
        wrB[k] = *(const u64*)&wsm[pl * 104 + k * 4 + 2];
    }

    for (int it = 0; it < 8; ++it) {
        const int c = c0 + cq + (it << 3);
        const u64* xb = g_xdup + (size_t)(b * CIN + c) * XPP + ph * XP + pw;
        u64 accA = 0, accB = 0;
        #pragma unroll
        for (int k = 0; k < 25; ++k) {
            u64 xx = xb[(k / 5) * XP + (k % 5)];
            ffma2(accA, xx, wrA[k]);
            ffma2(accB, xx, wrB[k]);
        }
        float2 a = unpack2(accA), bb = unpack2(accB);
        *reinterpret_cast<float4*>(out + (size_t)(b * CIN + c) * (HWB * 4) + 4 * p)
            = make_float4(a.x, a.y, bb.x, bb.y);
    }
}

// ---------------------------------------------------------------------------
extern "C" void kernel_launch(void* const* d_in, const int* in_sizes, int n_in,
                              void* d_out, int out_size)
{
    const float* x      = (const float*)d_in[0];   // (2,256,40,40)
    const float* w_comp = (const float*)d_in[1];   // (64,256,1,1)
    const float* w_enc  = (const float*)d_in[2];   // (100,64,3,3)
    float* out = (float*)d_out;                    // (2,256,80,80)

    k1_compress  <<<dim3(20, 8, 2),  640>>>(x, w_comp);
    k2_encoder   <<<dim3(25, 10, 2), 256>>>(w_enc);
    k3_reassemble<<<dim3(50, 4, 2),  256>>>(out);
}